// round 12
// baseline (speedup 1.0000x reference)
#include <cuda_runtime.h>
#include <cuda_fp16.h>
#include <cstdint>

#define N_IMG 16
#define C_IN  256
#define H_IN  128
#define W_IN  128
#define HB    129
#define C_OUT 512

// ---- device scratch (allowed: __device__ globals) ----
__device__ __align__(256) __half g_act[(size_t)N_IMG * HB * HB * C_IN];  // fp16 activations (unscaled)
__device__ __align__(256) __half g_w[(size_t)C_OUT * 9 * C_IN];          // fp16 weights [oc][tap][ic]

// ---------------------------------------------------------------------------
// helpers (base sm_103-safe PTX only: ldmatrix / mma.sync / cp.async)
// ---------------------------------------------------------------------------
__device__ __forceinline__ uint32_t s2u(const void* p) {
  uint32_t a;
  asm("{ .reg .u64 t; cvta.to.shared.u64 t, %1; cvt.u32.u64 %0, t; }" : "=r"(a) : "l"(p));
  return a;
}
__device__ __forceinline__ void cpa16(uint32_t d, const void* s) {
  asm volatile("cp.async.cg.shared.global [%0], [%1], 16;" :: "r"(d), "l"(s));
}
__device__ __forceinline__ void cpa_commit() {
  asm volatile("cp.async.commit_group;" ::: "memory");
}
template <int N>
__device__ __forceinline__ void cpa_wait() {
  asm volatile("cp.async.wait_group %0;" :: "n"(N) : "memory");
}
__device__ __forceinline__ void ldm4(uint32_t* r, uint32_t addr) {
  asm volatile("ldmatrix.sync.aligned.m8n8.x4.shared.b16 {%0,%1,%2,%3}, [%4];"
               : "=r"(r[0]), "=r"(r[1]), "=r"(r[2]), "=r"(r[3]) : "r"(addr));
}
// fp16-accumulator HMMA: D(f16x4 in 2 regs) = A*B + D
__device__ __forceinline__ void mma16816h(uint32_t* d, const uint32_t* a,
                                          uint32_t b0, uint32_t b1) {
  asm volatile(
      "mma.sync.aligned.m16n8k16.row.col.f16.f16.f16.f16 "
      "{%0,%1}, {%2,%3,%4,%5}, {%6,%7}, {%0,%1};"
      : "+r"(d[0]), "+r"(d[1])
      : "r"(a[0]), "r"(a[1]), "r"(a[2]), "r"(a[3]), "r"(b0), "r"(b1));
}
__device__ __forceinline__ uint32_t swz(uint32_t x) { return x ^ ((x >> 3) & 0x70); }

// ---------------------------------------------------------------------------
// Kernel 1: weight cast.  w[oc][ic][kh][kw] fp32 -> w[oc][tap][ic] fp16
// ---------------------------------------------------------------------------
__global__ void __launch_bounds__(256) wsplit_kernel(const float* __restrict__ w) {
  const int idx = blockIdx.x * 256 + threadIdx.x;  // < 512*9*256 exactly
  const int oc = idx / (9 * C_IN);
  const int r = idx - oc * 9 * C_IN;
  const int tap = r >> 8;
  const int ic = r & 255;
  g_w[idx] = __float2half(w[(oc * C_IN + ic) * 9 + tap]);
}

// ---------------------------------------------------------------------------
// Kernel 2: separable 4x4 blur -> NHWC fp16 (single copy, unscaled).
// ---------------------------------------------------------------------------
__global__ void __launch_bounds__(256) blur_kernel(const float* __restrict__ x,
                                                   const float* __restrict__ bk) {
  const int icg = blockIdx.x;   // 0..7
  const int h   = blockIdx.y;   // 0..128
  const int n   = blockIdx.z;   // 0..15
  const int t = threadIdx.x;
  const int ic_l = t & 31;
  const int ws = t >> 5;        // 0..7

  float vco[4], wco[4];
#pragma unroll
  for (int i = 0; i < 4; ++i) vco[i] = bk[i * 4] + bk[i * 4 + 1] + bk[i * 4 + 2] + bk[i * 4 + 3];
#pragma unroll
  for (int j = 0; j < 4; ++j) wco[j] = bk[j] + bk[4 + j] + bk[8 + j] + bk[12 + j];

  __shared__ __half sA[HB][32];

  const float* xp = x + (size_t)(n * C_IN + icg * 32 + ic_l) * (H_IN * W_IN);

  float4 v[6];
#pragma unroll
  for (int m = 0; m < 6; ++m) v[m] = make_float4(0.f, 0.f, 0.f, 0.f);
#pragma unroll
  for (int i = 0; i < 4; ++i) {
    const int r = h - 2 + i;
    if (r < 0 || r >= H_IN) continue;
    const float4* rp = reinterpret_cast<const float4*>(xp + r * W_IN);
    const float c = vco[i];
#pragma unroll
    for (int m = 0; m < 6; ++m) {
      const int c4 = ws * 4 - 1 + m;
      if (c4 >= 0 && c4 < 32) {
        const float4 d = rp[c4];
        v[m].x += c * d.x; v[m].y += c * d.y; v[m].z += c * d.z; v[m].w += c * d.w;
      }
    }
  }
  float vv[24];
#pragma unroll
  for (int m = 0; m < 6; ++m) {
    vv[4 * m] = v[m].x; vv[4 * m + 1] = v[m].y; vv[4 * m + 2] = v[m].z; vv[4 * m + 3] = v[m].w;
  }
#pragma unroll
  for (int k = 0; k < 17; ++k) {
    if (k == 16 && ws != 7) break;
    float s = wco[0] * vv[k + 2] + wco[1] * vv[k + 3] + wco[2] * vv[k + 4] + wco[3] * vv[k + 5];
    sA[ws * 16 + k][ic_l] = __float2half(s);
  }
  __syncthreads();

  const size_t base = ((size_t)(n * HB + h) * HB) * C_IN + icg * 32;
  for (int e = t; e < HB * 32; e += 256) {
    const int w = e >> 5, il = e & 31;
    g_act[base + (size_t)w * C_IN + il] = sA[w][il];
  }
}

// ---------------------------------------------------------------------------
// Kernel 3: mma.sync fp16 implicit GEMM, fat tiles, 3-stage pipeline.
// fp16 accumulators within a stage (96 products), promoted to fp32 per stage.
// CTA: 128 oc x 256 spatial (4 out rows x 64 cols). 8 warps (2 M x 4 N),
// warp tile 64x64. 24 stages, triple-buffered, one barrier/stage.
// ---------------------------------------------------------------------------
#define ST_A 0
#define ST_B 24576
#define STAGE 57600
#define SMEM_BYTES (3 * STAGE)   // 172800

extern __shared__ char csm[];

__global__ void __launch_bounds__(256, 1) conv_mma_kernel(const float* __restrict__ bias,
                                                          float* __restrict__ out) {
  const int t = threadIdx.x;
  const int l = t & 31, w = t >> 5;
  const int wm = w >> 2, wn = w & 3;         // warp = 64 oc x (output row wn)
  const int ocg = blockIdx.x;                // 0..3
  const int by = blockIdx.y;                 // 0..255
  const int n = by >> 4, rg = by & 15;
  const int oh0 = rg * 4;
  const int oc0 = ocg * 128;
  const uint32_t sb = s2u(csm);

  // ---- staging precomputes ----
  uint32_t a_sw[6], a_g[6];
#pragma unroll
  for (int k = 0; k < 6; ++k) {
    const int idx = t + k * 256;
    const int c = idx & 3, rowi = idx >> 2;
    const int kw = rowi >> 7, oc = rowi & 127;
    a_sw[k] = swz((uint32_t)(kw * 8192 + oc * 64 + c * 16));
    a_g[k] = (uint32_t)(((oc0 + oc) * 9 + kw) * C_IN + c * 8);  // + kh*768 + ic0
  }
  uint32_t b_sw[9], b_g[9];
#pragma unroll
  for (int k = 0; k < 9; ++k) {
    const int idx = t + k * 256;
    const int c = idx & 3;
    const uint32_t pp = (uint32_t)(idx >> 2);
    const uint32_t j = pp / 129u;
    const uint32_t colw = pp - j * 129u;
    b_sw[k] = swz(pp * 64 + c * 16);
    b_g[k] = (2 * j * HB + colw) * C_IN + c * 8;   // + brow0 at use
  }

  // ---- compute-side precomputes ----
  const int rl = l & 15, chh = l >> 4;
  uint32_t aOff[4], aMask[4];
#pragma unroll
  for (int i = 0; i < 4; ++i) {
    const int m = wm * 64 + i * 16 + rl;
    aOff[i] = (uint32_t)(m * 64 + chh * 16);
    aMask[i] = (uint32_t)((m & 14) << 3);
  }
  int pixB[4];
#pragma unroll
  for (int b = 0; b < 4; ++b) pixB[b] = wn * 129 + 32 * b + 2 * rl;

  float acc[4][8][4];
  uint32_t acc16[4][8][2];
#pragma unroll
  for (int i = 0; i < 4; ++i)
#pragma unroll
    for (int j = 0; j < 8; ++j) {
#pragma unroll
      for (int p = 0; p < 4; ++p) acc[i][j][p] = 0.f;
      acc16[i][j][0] = 0u; acc16[i][j][1] = 0u;
    }

  auto stage = [&](int s) {
    const int chunk = s / 3, kh = s - chunk * 3;
    const int ic0 = chunk * 32;
    const uint32_t stb = sb + (uint32_t)(s % 3) * STAGE;
    const uint32_t aadd = (uint32_t)(kh * 3 * C_IN + ic0);
    const uint32_t brow0 = (uint32_t)((n * HB + 2 * oh0 + kh) * HB) * C_IN + ic0;
#pragma unroll
    for (int k = 0; k < 6; ++k) cpa16(stb + ST_A + a_sw[k], g_w + a_g[k] + aadd);
#pragma unroll
    for (int k = 0; k < 9; ++k) {
      if (k < 8 || t < 16) cpa16(stb + ST_B + b_sw[k], g_act + brow0 + b_g[k]);
    }
    cpa_commit();
  };

  stage(0);
  stage(1);

  for (int s = 0; s < 24; ++s) {
    __syncthreads();                 // all warps done with buf[(s-1)%3] == buf[(s+2)%3]
    if (s + 2 < 24) {
      stage(s + 2);
      cpa_wait<2>();                 // stage s complete
    } else if (s + 1 < 24) {
      cpa_wait<1>();
    } else {
      cpa_wait<0>();
    }

    const uint32_t stb = sb + (uint32_t)(s % 3) * STAGE;
#pragma unroll
    for (int kw = 0; kw < 3; ++kw) {
      const uint32_t kwq = (uint32_t)(kw * 8192);
#pragma unroll
      for (int kk = 0; kk < 2; ++kk) {
        const uint32_t kq = (uint32_t)(kk * 32);
        uint32_t a[4][4];
#pragma unroll
        for (int i = 0; i < 4; ++i) ldm4(a[i], stb + ST_A + ((aOff[i] + kwq + kq) ^ aMask[i]));
        uint32_t bf[4][4];
#pragma unroll
        for (int b = 0; b < 4; ++b) {
          const int pix = pixB[b] + kw;
          const uint32_t bB = (uint32_t)(pix * 64 + chh * 16);
          const uint32_t bM = (uint32_t)((pix & 14) << 3);
          ldm4(bf[b], stb + ST_B + ((bB + kq) ^ bM));
        }
#pragma unroll
        for (int i = 0; i < 4; ++i)
#pragma unroll
          for (int b = 0; b < 4; ++b) {
            mma16816h(acc16[i][2 * b], a[i], bf[b][0], bf[b][2]);
            mma16816h(acc16[i][2 * b + 1], a[i], bf[b][1], bf[b][3]);
          }
      }
    }

    // ---- promote fp16 stage-accumulators into fp32, reset ----
#pragma unroll
    for (int i = 0; i < 4; ++i)
#pragma unroll
      for (int j = 0; j < 8; ++j) {
        const float2 f0 = __half22float2(*reinterpret_cast<const __half2*>(&acc16[i][j][0]));
        const float2 f1 = __half22float2(*reinterpret_cast<const __half2*>(&acc16[i][j][1]));
        acc[i][j][0] += f0.x; acc[i][j][1] += f0.y;
        acc[i][j][2] += f1.x; acc[i][j][3] += f1.y;
        acc16[i][j][0] = 0u; acc16[i][j][1] = 0u;
      }
  }

  // ---- epilogue: scale (EqualizedLR 1/48) + bias + direct float2 stores ----
  const float kS = 0.020833333333333332f;
  const int q = l >> 2, r2 = l & 3;
#pragma unroll
  for (int i = 0; i < 4; ++i) {
    const int ocA = oc0 + wm * 64 + i * 16 + q;
    const float bvA = bias[ocA];
    const float bvB = bias[ocA + 8];
    float* baseA = out + ((size_t)(n * C_OUT + ocA)) * 4096 + (oh0 + wn) * 64;
    float* baseB = baseA + (size_t)8 * 4096;
#pragma unroll
    for (int jj = 0; jj < 8; ++jj) {
      const int col = jj * 8 + 2 * r2;
      float2 v0 = make_float2(acc[i][jj][0] * kS + bvA, acc[i][jj][1] * kS + bvA);
      float2 v1 = make_float2(acc[i][jj][2] * kS + bvB, acc[i][jj][3] * kS + bvB);
      *reinterpret_cast<float2*>(baseA + col) = v0;
      *reinterpret_cast<float2*>(baseB + col) = v1;
    }
  }
}

// ---------------------------------------------------------------------------
extern "C" void kernel_launch(void* const* d_in, const int* in_sizes, int n_in,
                              void* d_out, int out_size) {
  (void)in_sizes; (void)n_in; (void)out_size;
  const float* x    = (const float*)d_in[0];  // [16,256,128,128]
  const float* wgt  = (const float*)d_in[1];  // [512,256,3,3]
  const float* bias = (const float*)d_in[2];  // [512]
  const float* bk   = (const float*)d_in[3];  // [4,4]
  float* out = (float*)d_out;                 // [16,512,64,64]

  cudaFuncSetAttribute(conv_mma_kernel, cudaFuncAttributeMaxDynamicSharedMemorySize,
                       SMEM_BYTES);
  wsplit_kernel<<<(C_OUT * 9 * C_IN) / 256, 256>>>(wgt);
  blur_kernel<<<dim3(8, HB, N_IMG), 256>>>(x, bk);
  conv_mma_kernel<<<dim3(4, 256), 256, SMEM_BYTES>>>(bias, out);
}

// round 15
// speedup vs baseline: 1.1016x; 1.1016x over previous
#include <cuda_runtime.h>
#include <cuda_fp16.h>
#include <cstdint>

#define N_IMG 16
#define C_IN  256
#define H_IN  128
#define W_IN  128
#define HB    129
#define C_OUT 512

// ---- device scratch (allowed: __device__ globals) ----
__device__ __align__(256) __half g_act[(size_t)N_IMG * HB * HB * C_IN];  // fp16 activations (unscaled)
__device__ __align__(256) __half g_w[(size_t)C_OUT * 9 * C_IN];          // fp16 weights [oc][tap][ic]

// ---------------------------------------------------------------------------
// helpers (base sm_103-safe PTX only: ldmatrix / mma.sync / cp.async)
// ---------------------------------------------------------------------------
__device__ __forceinline__ uint32_t s2u(const void* p) {
  uint32_t a;
  asm("{ .reg .u64 t; cvta.to.shared.u64 t, %1; cvt.u32.u64 %0, t; }" : "=r"(a) : "l"(p));
  return a;
}
__device__ __forceinline__ void cpa16(uint32_t d, const void* s) {
  asm volatile("cp.async.cg.shared.global [%0], [%1], 16;" :: "r"(d), "l"(s));
}
__device__ __forceinline__ void cpa_commit() {
  asm volatile("cp.async.commit_group;" ::: "memory");
}
template <int N>
__device__ __forceinline__ void cpa_wait() {
  asm volatile("cp.async.wait_group %0;" :: "n"(N) : "memory");
}
__device__ __forceinline__ void ldm4(uint32_t* r, uint32_t addr) {
  asm volatile("ldmatrix.sync.aligned.m8n8.x4.shared.b16 {%0,%1,%2,%3}, [%4];"
               : "=r"(r[0]), "=r"(r[1]), "=r"(r[2]), "=r"(r[3]) : "r"(addr));
}
__device__ __forceinline__ void mma16816(float* d, const uint32_t* a,
                                         uint32_t b0, uint32_t b1) {
  asm volatile(
      "mma.sync.aligned.m16n8k16.row.col.f32.f16.f16.f32 "
      "{%0,%1,%2,%3}, {%4,%5,%6,%7}, {%8,%9}, {%0,%1,%2,%3};"
      : "+f"(d[0]), "+f"(d[1]), "+f"(d[2]), "+f"(d[3])
      : "r"(a[0]), "r"(a[1]), "r"(a[2]), "r"(a[3]), "r"(b0), "r"(b1));
}

// ---------------------------------------------------------------------------
// Kernel 1: weight cast.  w[oc][ic][kh][kw] fp32 -> w[oc][tap][ic] fp16
// ---------------------------------------------------------------------------
__global__ void __launch_bounds__(256) wsplit_kernel(const float* __restrict__ w) {
  const int idx = blockIdx.x * 256 + threadIdx.x;  // < 512*9*256 exactly
  const int oc = idx / (9 * C_IN);
  const int r = idx - oc * 9 * C_IN;
  const int tap = r >> 8;
  const int ic = r & 255;
  g_w[idx] = __float2half(w[(oc * C_IN + ic) * 9 + tap]);
}

// ---------------------------------------------------------------------------
// Kernel 2: separable 4x4 blur -> NHWC fp16 (single copy, unscaled).
// ---------------------------------------------------------------------------
__global__ void __launch_bounds__(256) blur_kernel(const float* __restrict__ x,
                                                   const float* __restrict__ bk) {
  const int icg = blockIdx.x;   // 0..7
  const int h   = blockIdx.y;   // 0..128
  const int n   = blockIdx.z;   // 0..15
  const int t = threadIdx.x;
  const int ic_l = t & 31;
  const int ws = t >> 5;        // 0..7

  float vco[4], wco[4];
#pragma unroll
  for (int i = 0; i < 4; ++i) vco[i] = bk[i * 4] + bk[i * 4 + 1] + bk[i * 4 + 2] + bk[i * 4 + 3];
#pragma unroll
  for (int j = 0; j < 4; ++j) wco[j] = bk[j] + bk[4 + j] + bk[8 + j] + bk[12 + j];

  __shared__ __half sA[HB][32];

  const float* xp = x + (size_t)(n * C_IN + icg * 32 + ic_l) * (H_IN * W_IN);

  float4 v[6];
#pragma unroll
  for (int m = 0; m < 6; ++m) v[m] = make_float4(0.f, 0.f, 0.f, 0.f);
#pragma unroll
  for (int i = 0; i < 4; ++i) {
    const int r = h - 2 + i;
    if (r < 0 || r >= H_IN) continue;
    const float4* rp = reinterpret_cast<const float4*>(xp + r * W_IN);
    const float c = vco[i];
#pragma unroll
    for (int m = 0; m < 6; ++m) {
      const int c4 = ws * 4 - 1 + m;
      if (c4 >= 0 && c4 < 32) {
        const float4 d = rp[c4];
        v[m].x += c * d.x; v[m].y += c * d.y; v[m].z += c * d.z; v[m].w += c * d.w;
      }
    }
  }
  float vv[24];
#pragma unroll
  for (int m = 0; m < 6; ++m) {
    vv[4 * m] = v[m].x; vv[4 * m + 1] = v[m].y; vv[4 * m + 2] = v[m].z; vv[4 * m + 3] = v[m].w;
  }
#pragma unroll
  for (int k = 0; k < 17; ++k) {
    if (k == 16 && ws != 7) break;
    float s = wco[0] * vv[k + 2] + wco[1] * vv[k + 3] + wco[2] * vv[k + 4] + wco[3] * vv[k + 5];
    sA[ws * 16 + k][ic_l] = __float2half(s);
  }
  __syncthreads();

  const size_t base = ((size_t)(n * HB + h) * HB) * C_IN + icg * 32;
  for (int e = t; e < HB * 32; e += 256) {
    const int w = e >> 5, il = e & 31;
    g_act[base + (size_t)w * C_IN + il] = sA[w][il];
  }
}

// ---------------------------------------------------------------------------
// Kernel 3: mma.sync fp16 implicit GEMM, fat tiles, fat stages.
// CTA: 128 oc x 256 spatial (4 out rows x 64 cols). 8 warps (2 M x 4 N),
// warp tile 64x64, fp32 accumulators.
// Stage = (ic-chunk of 64, kh): 4 input rows x 129 pix x 128B + 3 kw weight
// tiles. 12 stages, double-buffered (225KB).
// RACE-FREE ordering (CUTLASS / R8-proven): issue(s+1) -> wait -> barrier ->
// compute(s) -> barrier. cp.async.wait_group only covers the executing
// thread's groups; the post-wait barrier is what makes OTHER threads'
// copies visible. The trailing barrier protects the buffer the next issue
// overwrites.
// ---------------------------------------------------------------------------
#define ST_A 0
#define ST_B 49152
#define STAGE 115200
#define SMEM_BYTES (2 * STAGE)   // 230400

extern __shared__ char csm[];

__global__ void __launch_bounds__(256, 1) conv_mma_kernel(const float* __restrict__ bias,
                                                          float* __restrict__ out) {
  const int t = threadIdx.x;
  const int l = t & 31, w = t >> 5;
  const int wm = w >> 2, wn = w & 3;         // warp = 64 oc x (output row wn)
  const int ocg = blockIdx.x;                // 0..3
  const int by = blockIdx.y;                 // 0..255
  const int n = by >> 4, rg = by & 15;
  const int oh0 = rg * 4;
  const int oc0 = ocg * 128;
  const uint32_t sb = s2u(csm);

  // ---- staging precomputes (global offsets; smem offsets derived inline) ----
  // A: 3072 16B-chunks: idx -> c(0..7), row = kw*128 + oc
  uint32_t a_g[12];
#pragma unroll
  for (int k = 0; k < 12; ++k) {
    const int idx = t + k * 256;
    const int c = idx & 7, rowi = idx >> 3;
    const int kw = rowi >> 7, oc = rowi & 127;
    a_g[k] = (uint32_t)(((oc0 + oc) * 9 + kw) * C_IN + c * 8);  // + kh*768 + ic0
  }
  // B: 4128 16B-chunks: idx -> c(0..7), pixel pp(0..515) = j*129 + colw
  uint32_t b_g[17];
#pragma unroll
  for (int k = 0; k < 17; ++k) {
    const int idx = t + k * 256;
    const int c = idx & 7;
    const uint32_t pp = (uint32_t)(idx >> 3);
    const uint32_t j = pp / 129u;
    const uint32_t colw = pp - j * 129u;
    b_g[k] = (2 * j * HB + colw) * C_IN + c * 8;   // + brow0 at use
  }

  // ---- compute-side precomputes ----
  const int rl = l & 15, chh = l >> 4;
  uint32_t aOff[4], aMask[4];
#pragma unroll
  for (int i = 0; i < 4; ++i) {
    const int m = wm * 64 + i * 16 + rl;
    aOff[i] = (uint32_t)(m * 128 + chh * 16);
    aMask[i] = (uint32_t)((m & 7) << 4);
  }
  int pixB[4];
#pragma unroll
  for (int b = 0; b < 4; ++b) pixB[b] = wn * 129 + 32 * b + 2 * rl;

  float acc[4][8][4];
#pragma unroll
  for (int i = 0; i < 4; ++i)
#pragma unroll
    for (int j = 0; j < 8; ++j)
#pragma unroll
      for (int p = 0; p < 4; ++p) acc[i][j][p] = 0.f;

  auto stage = [&](int s) {
    const int chunk = s / 3, kh = s - chunk * 3;
    const int ic0 = chunk * 64;
    const uint32_t stb = sb + (uint32_t)(s & 1) * STAGE;
    const uint32_t aadd = (uint32_t)(kh * 3 * C_IN + ic0);
    const uint32_t brow0 = (uint32_t)((n * HB + 2 * oh0 + kh) * HB) * C_IN + ic0;
#pragma unroll
    for (int k = 0; k < 12; ++k) {
      const uint32_t idx = (uint32_t)(t + k * 256);
      const uint32_t sw = (idx * 16) ^ (((idx >> 3) & 7) << 4);
      cpa16(stb + ST_A + sw, g_w + a_g[k] + aadd);
    }
#pragma unroll
    for (int k = 0; k < 17; ++k) {
      if (k < 16 || t < 32) {
        const uint32_t idx = (uint32_t)(t + k * 256);
        const uint32_t sw = (idx * 16) ^ (((idx >> 3) & 7) << 4);
        cpa16(stb + ST_B + sw, g_act + brow0 + b_g[k]);
      }
    }
    cpa_commit();
  };

  stage(0);

  for (int s = 0; s < 12; ++s) {
    if (s + 1 < 12) {
      stage(s + 1);          // into buf (s+1)&1 — safe: trailing barrier of s-1
      cpa_wait<1>();         // this thread's stage-s copies complete
    } else {
      cpa_wait<0>();
    }
    __syncthreads();         // ALL threads waited -> ALL stage-s copies visible

    const uint32_t stb = sb + (uint32_t)(s & 1) * STAGE;
#pragma unroll
    for (int kw = 0; kw < 3; ++kw) {
      const uint32_t kwq = (uint32_t)(kw * 16384);
#pragma unroll
      for (int kk = 0; kk < 4; ++kk) {
        const uint32_t kq = (uint32_t)(kk * 32);
        uint32_t a[4][4];
#pragma unroll
        for (int i = 0; i < 4; ++i) ldm4(a[i], stb + ST_A + kwq + ((aOff[i] + kq) ^ aMask[i]));
        uint32_t bf[4][4];
#pragma unroll
        for (int b = 0; b < 4; ++b) {
          const int pix = pixB[b] + kw;
          const uint32_t bB = (uint32_t)(pix * 128 + chh * 16);
          const uint32_t bM = (uint32_t)((pix & 7) << 4);
          ldm4(bf[b], stb + ST_B + ((bB + kq) ^ bM));
        }
#pragma unroll
        for (int i = 0; i < 4; ++i)
#pragma unroll
          for (int b = 0; b < 4; ++b) {
            mma16816(acc[i][2 * b], a[i], bf[b][0], bf[b][2]);
            mma16816(acc[i][2 * b + 1], a[i], bf[b][1], bf[b][3]);
          }
      }
    }
    __syncthreads();         // done reading buf s&1 before iter s+1 overwrites it
  }

  // ---- epilogue: scale (EqualizedLR 1/48) + bias + direct float2 stores ----
  const float kS = 0.020833333333333332f;
  const int q = l >> 2, r2 = l & 3;
#pragma unroll
  for (int i = 0; i < 4; ++i) {
    const int ocA = oc0 + wm * 64 + i * 16 + q;
    const float bvA = bias[ocA];
    const float bvB = bias[ocA + 8];
    float* baseA = out + ((size_t)(n * C_OUT + ocA)) * 4096 + (oh0 + wn) * 64;
    float* baseB = baseA + (size_t)8 * 4096;
#pragma unroll
    for (int jj = 0; jj < 8; ++jj) {
      const int col = jj * 8 + 2 * r2;
      float2 v0 = make_float2(acc[i][jj][0] * kS + bvA, acc[i][jj][1] * kS + bvA);
      float2 v1 = make_float2(acc[i][jj][2] * kS + bvB, acc[i][jj][3] * kS + bvB);
      *reinterpret_cast<float2*>(baseA + col) = v0;
      *reinterpret_cast<float2*>(baseB + col) = v1;
    }
  }
}

// ---------------------------------------------------------------------------
extern "C" void kernel_launch(void* const* d_in, const int* in_sizes, int n_in,
                              void* d_out, int out_size) {
  (void)in_sizes; (void)n_in; (void)out_size;
  const float* x    = (const float*)d_in[0];  // [16,256,128,128]
  const float* wgt  = (const float*)d_in[1];  // [512,256,3,3]
  const float* bias = (const float*)d_in[2];  // [512]
  const float* bk   = (const float*)d_in[3];  // [4,4]
  float* out = (float*)d_out;                 // [16,512,64,64]

  cudaFuncSetAttribute(conv_mma_kernel, cudaFuncAttributeMaxDynamicSharedMemorySize,
                       SMEM_BYTES);
  wsplit_kernel<<<(C_OUT * 9 * C_IN) / 256, 256>>>(wgt);
  blur_kernel<<<dim3(8, HB, N_IMG), 256>>>(x, bk);
  conv_mma_kernel<<<dim3(4, 256), 256, SMEM_BYTES>>>(bias, out);
}